// round 3
// baseline (speedup 1.0000x reference)
#include <cuda_runtime.h>
#include <math.h>

#define FULLMASK 0xffffffffu

#define BB   2
#define NN   2048
#define HH   8
#define HID  128
#define VD   16
#define BN   (BB * NN)
// locality=5 -> pos=0.05*2047=102.35 -> need 103rd smallest (0-indexed 102)
#define KTH  103

// GEMM smem: Ws 128k x 64cols f32 (32KB) + A2 64rows x stride130 ull (66.56KB)
#define GEMM_SMEM (32768 + 64 * 130 * 8)
// Attention smem: full v, 2048 rows x stride-18 f32
#define ATTN_SMEM (NN * 18 * 4)

typedef unsigned long long ull;

// ---------------- scratch (device globals; no allocation) ----------------
__device__ float  g_en[BN * HID];
__device__ float  g_x [BN * HID];
__device__ float  g_h [BN * HID];
__device__ float  g_t [BN * HID];
__device__ float  g_r [BN * HID];
__device__ float  g_v [BN * HID];
__device__ float  g_wcat[HID * HID];
__device__ float2 g_rowstats[BN];

// ---------------- f32x2 packed helpers ----------------
__device__ __forceinline__ ull pack2(float x, float y) {
    ull r;
    asm("mov.b64 %0, {%1, %2};" : "=l"(r) : "r"(__float_as_uint(x)), "r"(__float_as_uint(y)));
    return r;
}
__device__ __forceinline__ void unpack2(ull u, float& x, float& y) {
    unsigned a, b;
    asm("mov.b64 {%0, %1}, %2;" : "=r"(a), "=r"(b) : "l"(u));
    x = __uint_as_float(a); y = __uint_as_float(b);
}
__device__ __forceinline__ ull fma2(ull a, ull b, ull c) {
    ull d;
    asm("fma.rn.f32x2 %0, %1, %2, %3;" : "=l"(d) : "l"(a), "l"(b), "l"(c));
    return d;
}
__device__ __forceinline__ ull add2(ull a, ull b) {
    ull d;
    asm("add.rn.f32x2 %0, %1, %2;" : "=l"(d) : "l"(a), "l"(b));
    return d;
}
__device__ __forceinline__ float ex2f(float x) {
    float r;
    asm("ex2.approx.f32 %0, %1;" : "=f"(r) : "f"(x));
    return r;
}

__device__ __forceinline__ float gelu_f(float x) {
    // exact (erf) gelu, matching jax.nn.gelu(approximate=False)
    return 0.5f * x * (1.0f + erff(x * 0.70710678118654752f));
}

// ---------------- per-row order statistics of m_dist ----------------
// For each of the B*N rows (length N): min and the 103rd-smallest value.
// Monotonicity of m -> m*r^2 makes these sufficient for the softmax max and
// the percentile mask of both masked mhpas, for all heads. Exact selection
// via binary search on the nonnegative-float bit pattern (values in [0,1)).
__global__ void rowstats_kernel(const float* __restrict__ md, float2* __restrict__ rs) {
    int warp = threadIdx.x >> 5, lane = threadIdx.x & 31;
    int row = blockIdx.x * 8 + warp;
    const float* p = md + (size_t)row * NN + lane;
    unsigned mu[64];
    float mn = 1e30f;
#pragma unroll
    for (int i = 0; i < 64; ++i) {
        float x = p[i * 32];
        mn = fminf(mn, x);
        mu[i] = __float_as_uint(x);
    }
#pragma unroll
    for (int off = 16; off; off >>= 1)
        mn = fminf(mn, __shfl_xor_sync(FULLMASK, mn, off));

    unsigned lo = 0u, hi = 0x3F800000u;  // bit patterns of [0,1)
    while (hi - lo > 1u) {
        unsigned mid = (lo + hi) >> 1;
        int c = 0;
#pragma unroll
        for (int i = 0; i < 64; ++i) c += (mu[i] <= mid) ? 1 : 0;
        c = __reduce_add_sync(FULLMASK, c);
        if (c >= KTH) hi = mid; else lo = mid;
    }
    if (lane == 0) rs[row] = make_float2(mn, __uint_as_float(hi));
}

// ---------------- encoder: gelu(inputs @ en_W + en_b), K=3 ----------------
__global__ void enc_kernel(const float* __restrict__ inp, const float* __restrict__ W,
                           const float* __restrict__ bvec, float* __restrict__ out) {
    int token = blockIdx.x, c = threadIdx.x;
    float x0 = inp[token * 3 + 0];
    float x1 = inp[token * 3 + 1];
    float x2 = inp[token * 3 + 2];
    float s = bvec[c];
    s = fmaf(x0, W[c], s);
    s = fmaf(x1, W[HID + c], s);
    s = fmaf(x2, W[2 * HID + c], s);
    out[(size_t)token * HID + c] = gelu_f(s);
}

// ---------------- repack head weights (H,HID,VD) -> (HID, H*VD) ----------------
__global__ void repack_kernel(const float* __restrict__ w, float* __restrict__ wc) {
    int idx = blockIdx.x * 256 + threadIdx.x;  // 16384 total
    int k = idx >> 7, c = idx & 127;
    wc[idx] = w[(c >> 4) * (HID * VD) + k * VD + (c & 15)];
}

// ---------------- 4096x128 @ 128x128 GEMM (f32x2, col-split) ----------------
// Grid: (BN/64, 2). CTA: 64 rows x 64 cols. A staged in smem packed (a,a) as
// f32x2 (row-major, stride 130 ull). W staged [k][64] f32. Per k per thread:
// 1 LDS.128 (w) + 2 packs + 4 LDS.64 (a, half-warp broadcast) + 8 FMA2.
__global__ void __launch_bounds__(256) gemm2_kernel(
    const float* __restrict__ A, const float* __restrict__ W,
    const float* __restrict__ bias, const float* __restrict__ res,
    float* __restrict__ out, int act)
{
    extern __shared__ char sm[];
    float* Ws = (float*)sm;                 // [k][64]
    ull*   A2 = (ull*)(sm + 32768);         // [row][k], stride 130

    int tid = threadIdx.x;
    int colblk = blockIdx.y;
    int row0 = blockIdx.x * 64;
    int cbase = colblk * 64;

    // stage W half
#pragma unroll
    for (int idx = tid; idx < 128 * 16; idx += 256) {
        int k = idx >> 4, c4 = idx & 15;
        float4 wv = *(const float4*)(W + (size_t)k * HID + cbase + c4 * 4);
        *(float4*)(Ws + k * 64 + c4 * 4) = wv;
    }
    // stage A packed (a,a)
#pragma unroll
    for (int idx = tid; idx < 64 * 32; idx += 256) {
        int r = idx >> 5, k4 = idx & 31;
        float4 a = *(const float4*)(A + (size_t)(row0 + r) * HID + k4 * 4);
        ull* dst = A2 + r * 130 + k4 * 4;
        dst[0] = pack2(a.x, a.x);
        dst[1] = pack2(a.y, a.y);
        dst[2] = pack2(a.z, a.z);
        dst[3] = pack2(a.w, a.w);
    }
    __syncthreads();

    int rg = tid & 15;       // row group: rows rg + 16*i
    int cg = tid >> 4;       // col group: cols 4*cg .. 4*cg+3
    ull acc[4][2];
#pragma unroll
    for (int i = 0; i < 4; ++i) { acc[i][0] = 0ull; acc[i][1] = 0ull; }

    const ull* a0 = A2 + rg * 130;
#pragma unroll 4
    for (int k = 0; k < HID; ++k) {
        float4 wv = *(const float4*)(Ws + k * 64 + cg * 4);
        ull w01 = pack2(wv.x, wv.y);
        ull w23 = pack2(wv.z, wv.w);
#pragma unroll
        for (int i = 0; i < 4; ++i) {
            ull a = a0[i * (16 * 130) + k];
            acc[i][0] = fma2(a, w01, acc[i][0]);
            acc[i][1] = fma2(a, w23, acc[i][1]);
        }
    }

    float b0 = 0.f, b1 = 0.f, b2 = 0.f, b3 = 0.f;
    if (bias) {
        float4 bv = *(const float4*)(bias + cbase + cg * 4);
        b0 = bv.x; b1 = bv.y; b2 = bv.z; b3 = bv.w;
    }
#pragma unroll
    for (int i = 0; i < 4; ++i) {
        int row = row0 + rg + 16 * i;
        float o0, o1, o2, o3;
        unpack2(acc[i][0], o0, o1);
        unpack2(acc[i][1], o2, o3);
        o0 += b0; o1 += b1; o2 += b2; o3 += b3;
        if (res) {
            float4 rv = *(const float4*)(res + (size_t)row * HID + cbase + cg * 4);
            o0 += rv.x; o1 += rv.y; o2 += rv.z; o3 += rv.w;
        }
        if (act) { o0 = gelu_f(o0); o1 = gelu_f(o1); o2 = gelu_f(o2); o3 = gelu_f(o3); }
        *(float4*)(out + (size_t)row * HID + cbase + cg * 4) = make_float4(o0, o1, o2, o3);
    }
}

// ---------------- fused percentile-softmax attention + gelu (f32x2) --------
// CTA: 512 threads = 16 warps x 4 rows = 64 rows, one (b,h). Full v (2048x16)
// resident in smem, stride 18 (conflict-free LDS.64). Lane <-> j slot: each
// warp-step covers 32 distinct j for 4 rows; exp computed ONCE per (i,j);
// 16 dims accumulated as 8 packed f32x2 FMAs.
template <int MASKED>
__global__ void __launch_bounds__(512, 1) attn2_kernel(
    const float* __restrict__ md, const float* __restrict__ v,
    const float* __restrict__ rvec, const float2* __restrict__ rs,
    float* __restrict__ out)
{
    extern __shared__ float vs[];   // [2048][18]
    int b = blockIdx.z, h = blockIdx.y;
    float rr = rvec[h];
    float r2 = rr * rr;
    const float L2E = 1.4426950408889634f;
    float nr2l = -r2 * L2E;

    int tid = threadIdx.x;
    int lane = tid & 31, warp = tid >> 5;
    int i0 = blockIdx.x * 64 + warp * 4;

    // stage full v_h into smem
    const float* vg = v + (size_t)b * NN * HID + h * VD;
    for (int idx = tid; idx < NN * 8; idx += 512) {
        int jj = idx >> 3, dd = (idx & 7) << 1;
        float2 val = *(const float2*)(vg + (size_t)jj * HID + dd);
        *(float2*)(vs + jj * 18 + dd) = val;
    }

    float msdl[4], s102[4], wsum[4];
    ull acc[4][8];
#pragma unroll
    for (int g = 0; g < 4; ++g) {
        float2 st = rs[b * NN + i0 + g];
        msdl[g] = (st.x * r2) * L2E;  // st.x*r2 == min_j(sd) exactly (monotone)
        s102[g] = st.y;
        wsum[g] = 0.f;
#pragma unroll
        for (int d = 0; d < 8; ++d) acc[g][d] = 0ull;
    }

    const float* mrow = md + ((size_t)b * NN + i0) * NN;

    __syncthreads();

    int j = lane;
    float mc[4];
#pragma unroll
    for (int g = 0; g < 4; ++g) mc[g] = mrow[(size_t)g * NN + j];

    for (int t = 0; t < NN / 32; ++t) {
        int jn = j + 32;
        if (jn >= NN) jn = j;        // harmless clamp on last iteration
        float mn_[4];
#pragma unroll
        for (int g = 0; g < 4; ++g) mn_[g] = mrow[(size_t)g * NN + jn];

        const ull* vrow = (const ull*)(vs + j * 18);
        ull v0 = vrow[0], v1 = vrow[1], v2 = vrow[2], v3 = vrow[3];
        ull v4 = vrow[4], v5 = vrow[5], v6 = vrow[6], v7 = vrow[7];

#pragma unroll
        for (int g = 0; g < 4; ++g) {
            float m = mc[g];
            float e = ex2f(fmaf(m, nr2l, msdl[g]));
            float w = MASKED ? ((m <= s102[g]) ? e : 0.f) : e;
            wsum[g] += w;
            ull wp = pack2(w, w);
            acc[g][0] = fma2(wp, v0, acc[g][0]);
            acc[g][1] = fma2(wp, v1, acc[g][1]);
            acc[g][2] = fma2(wp, v2, acc[g][2]);
            acc[g][3] = fma2(wp, v3, acc[g][3]);
            acc[g][4] = fma2(wp, v4, acc[g][4]);
            acc[g][5] = fma2(wp, v5, acc[g][5]);
            acc[g][6] = fma2(wp, v6, acc[g][6]);
            acc[g][7] = fma2(wp, v7, acc[g][7]);
        }
#pragma unroll
        for (int g = 0; g < 4; ++g) mc[g] = mn_[g];
        j = jn;
    }

    // butterfly reduce across 32 lanes (j slots)
#pragma unroll
    for (int off = 16; off; off >>= 1) {
#pragma unroll
        for (int g = 0; g < 4; ++g) {
            wsum[g] += __shfl_xor_sync(FULLMASK, wsum[g], off);
#pragma unroll
            for (int d = 0; d < 8; ++d) {
                ull o = __shfl_xor_sync(FULLMASK, acc[g][d], off);
                acc[g][d] = add2(acc[g][d], o);
            }
        }
    }

    if (lane < 4) {
        int g = lane;
        float inv = 1.0f / wsum[g];
        float o[16];
#pragma unroll
        for (int d = 0; d < 8; ++d) unpack2(acc[g][d], o[2 * d], o[2 * d + 1]);
#pragma unroll
        for (int e = 0; e < 16; ++e) o[e] = gelu_f(o[e] * inv);
        float* dst = out + (size_t)(b * NN + i0 + g) * HID + h * VD;
        *(float4*)(dst + 0)  = make_float4(o[0],  o[1],  o[2],  o[3]);
        *(float4*)(dst + 4)  = make_float4(o[4],  o[5],  o[6],  o[7]);
        *(float4*)(dst + 8)  = make_float4(o[8],  o[9],  o[10], o[11]);
        *(float4*)(dst + 12) = make_float4(o[12], o[13], o[14], o[15]);
    }
}

// ---------------- final 128 -> 1 projection ----------------
__global__ void final_kernel(const float* __restrict__ t, const float* __restrict__ W,
                             const float* __restrict__ bvec, float* __restrict__ out) {
    int warp = threadIdx.x >> 5, lane = threadIdx.x & 31;
    int token = blockIdx.x * 8 + warp;
    const float* p = t + (size_t)token * HID;
    float s = 0.f;
#pragma unroll
    for (int i = 0; i < 4; ++i) s = fmaf(p[lane + 32 * i], W[lane + 32 * i], s);
#pragma unroll
    for (int off = 16; off; off >>= 1) s += __shfl_xor_sync(FULLMASK, s, off);
    if (lane == 0) out[token] = s + bvec[0];
}

// ---------------- orchestration ----------------
static float* symf(const void* sym) {
    void* p = nullptr;
    cudaGetSymbolAddress(&p, sym);
    return (float*)p;
}

extern "C" void kernel_launch(void* const* d_in, const int* in_sizes, int n_in,
                              void* d_out, int out_size) {
    const float* md      = (const float*)d_in[0];
    const float* inputs  = (const float*)d_in[1];
    const float* en_W    = (const float*)d_in[2];
    const float* en_b    = (const float*)d_in[3];
    const float* down_r  = (const float*)d_in[4];
    const float* down_w  = (const float*)d_in[5];
    const float* mlp1_W1 = (const float*)d_in[6];
    const float* mlp1_b1 = (const float*)d_in[7];
    const float* mlp1_W2 = (const float*)d_in[8];
    const float* mlp1_b2 = (const float*)d_in[9];
    const float* w1_W    = (const float*)d_in[10];
    const float* w1_b    = (const float*)d_in[11];
    const float* pa_r    = (const float*)d_in[12];
    const float* pa_w    = (const float*)d_in[13];
    const float* blk_W1  = (const float*)d_in[14];
    const float* blk_b1  = (const float*)d_in[15];
    const float* blk_W2  = (const float*)d_in[16];
    const float* blk_b2  = (const float*)d_in[17];
    const float* wi_W    = (const float*)d_in[18];
    const float* wi_b    = (const float*)d_in[19];
    const float* up_r    = (const float*)d_in[20];
    const float* up_w    = (const float*)d_in[21];
    const float* mlp2_W1 = (const float*)d_in[22];
    const float* mlp2_b1 = (const float*)d_in[23];
    const float* mlp2_W2 = (const float*)d_in[24];
    const float* mlp2_b2 = (const float*)d_in[25];
    const float* w2_W    = (const float*)d_in[26];
    const float* w2_b    = (const float*)d_in[27];
    const float* de_W1   = (const float*)d_in[28];
    const float* de_b1   = (const float*)d_in[29];
    const float* de_W2   = (const float*)d_in[30];
    const float* de_b2   = (const float*)d_in[31];
    float* outp = (float*)d_out;

    float*  en = symf(g_en);
    float*  x  = symf(g_x);
    float*  hb = symf(g_h);
    float*  tb = symf(g_t);
    float*  rb = symf(g_r);
    float*  vb = symf(g_v);
    float*  wc = symf(g_wcat);
    float2* rsp;
    { void* p = nullptr; cudaGetSymbolAddress(&p, g_rowstats); rsp = (float2*)p; }

    cudaFuncSetAttribute(gemm2_kernel, cudaFuncAttributeMaxDynamicSharedMemorySize, GEMM_SMEM);
    cudaFuncSetAttribute(attn2_kernel<0>, cudaFuncAttributeMaxDynamicSharedMemorySize, ATTN_SMEM);
    cudaFuncSetAttribute(attn2_kernel<1>, cudaFuncAttributeMaxDynamicSharedMemorySize, ATTN_SMEM);

    dim3 ggrid(BN / 64, 2);
    dim3 agrid(NN / 64, HH, BB);

    rowstats_kernel<<<BN / 8, 256>>>(md, rsp);
    enc_kernel<<<BN, HID>>>(inputs, en_W, en_b, en);

    // ---- stage 1 (input en, masked mhpa) ----
    repack_kernel<<<64, 256>>>(down_w, wc);
    gemm2_kernel<<<ggrid, 256, GEMM_SMEM>>>(en, wc, nullptr, nullptr, vb, 0);
    attn2_kernel<1><<<agrid, 512, ATTN_SMEM>>>(md, vb, down_r, rsp, hb);
    gemm2_kernel<<<ggrid, 256, GEMM_SMEM>>>(en, w1_W, w1_b, nullptr, rb, 0);
    gemm2_kernel<<<ggrid, 256, GEMM_SMEM>>>(hb, mlp1_W1, mlp1_b1, nullptr, tb, 1);
    gemm2_kernel<<<ggrid, 256, GEMM_SMEM>>>(tb, mlp1_W2, mlp1_b2, rb, x, 1);

    // ---- 4 unmasked blocks ----
    for (int i = 0; i < 4; ++i) {
        repack_kernel<<<64, 256>>>(pa_w + (size_t)i * HH * HID * VD, wc);
        gemm2_kernel<<<ggrid, 256, GEMM_SMEM>>>(x, wc, nullptr, nullptr, vb, 0);
        attn2_kernel<0><<<agrid, 512, ATTN_SMEM>>>(md, vb, pa_r + (size_t)i * HH, rsp, hb);
        gemm2_kernel<<<ggrid, 256, GEMM_SMEM>>>(x, wi_W + (size_t)i * HID * HID, wi_b + (size_t)i * HID, nullptr, rb, 0);
        gemm2_kernel<<<ggrid, 256, GEMM_SMEM>>>(hb, blk_W1 + (size_t)i * HID * HID, blk_b1 + (size_t)i * HID, nullptr, tb, 1);
        gemm2_kernel<<<ggrid, 256, GEMM_SMEM>>>(tb, blk_W2 + (size_t)i * HID * HID, blk_b2 + (size_t)i * HID, rb, x, 1);
    }

    // ---- stage 2 (masked mhpa) ----
    repack_kernel<<<64, 256>>>(up_w, wc);
    gemm2_kernel<<<ggrid, 256, GEMM_SMEM>>>(x, wc, nullptr, nullptr, vb, 0);
    attn2_kernel<1><<<agrid, 512, ATTN_SMEM>>>(md, vb, up_r, rsp, hb);
    gemm2_kernel<<<ggrid, 256, GEMM_SMEM>>>(x, w2_W, w2_b, nullptr, rb, 0);
    gemm2_kernel<<<ggrid, 256, GEMM_SMEM>>>(hb, mlp2_W1, mlp2_b1, nullptr, tb, 1);
    gemm2_kernel<<<ggrid, 256, GEMM_SMEM>>>(tb, mlp2_W2, mlp2_b2, rb, x, 1);   // x = de

    // ---- decoder ----
    gemm2_kernel<<<ggrid, 256, GEMM_SMEM>>>(x, de_W1, de_b1, nullptr, tb, 1);
    final_kernel<<<BN / 8, 256>>>(tb, de_W2, de_b2, outp);
}

// round 4
// speedup vs baseline: 1.2229x; 1.2229x over previous
#include <cuda_runtime.h>
#include <math.h>

#define FULLMASK 0xffffffffu

#define BB   2
#define NN   2048
#define HH   8
#define HID  128
#define VD   16
#define BN   (BB * NN)
// locality=5 -> pos=0.05*2047=102.35 -> need 103rd smallest (0-indexed 102)
#define KTH  103

// GEMM smem: Ws [128][64] f32 (32KB) + As [32][128] f32 (16KB) = 48KB
#define GEMM_SMEM (32768 + 16384)
// Attention smem: full v, 2048 rows x stride-18 f32 = 144KB
#define ATTN_SMEM (NN * 18 * 4)

typedef unsigned long long ull;

// ---------------- scratch (device globals; no allocation) ----------------
__device__ float  g_en[BN * HID];
__device__ float  g_x [BN * HID];
__device__ float  g_h [BN * HID];
__device__ float  g_t [BN * HID];
__device__ float  g_r [BN * HID];
__device__ float  g_v [BN * HID];
__device__ float  g_wcat[HID * HID];
__device__ float2 g_rowstats[BN];

// ---------------- f32x2 packed helpers ----------------
__device__ __forceinline__ ull pack2(float x, float y) {
    ull r;
    asm("mov.b64 %0, {%1, %2};" : "=l"(r) : "r"(__float_as_uint(x)), "r"(__float_as_uint(y)));
    return r;
}
__device__ __forceinline__ void unpack2(ull u, float& x, float& y) {
    unsigned a, b;
    asm("mov.b64 {%0, %1}, %2;" : "=r"(a), "=r"(b) : "l"(u));
    x = __uint_as_float(a); y = __uint_as_float(b);
}
__device__ __forceinline__ ull fma2(ull a, ull b, ull c) {
    ull d;
    asm("fma.rn.f32x2 %0, %1, %2, %3;" : "=l"(d) : "l"(a), "l"(b), "l"(c));
    return d;
}
__device__ __forceinline__ ull add2(ull a, ull b) {
    ull d;
    asm("add.rn.f32x2 %0, %1, %2;" : "=l"(d) : "l"(a), "l"(b));
    return d;
}
__device__ __forceinline__ float ex2f(float x) {
    float r;
    asm("ex2.approx.f32 %0, %1;" : "=f"(r) : "f"(x));
    return r;
}

__device__ __forceinline__ float gelu_f(float x) {
    // exact (erf) gelu, matching jax.nn.gelu(approximate=False)
    return 0.5f * x * (1.0f + erff(x * 0.70710678118654752f));
}

// ---------------- per-row order statistics of m_dist ----------------
// For each of the B*N rows (length N): min and the 103rd-smallest value.
// Monotonicity of m -> m*r^2 makes these sufficient for the softmax max and
// the percentile mask of both masked mhpas, for all heads. Exact selection
// via binary search on the nonnegative-float bit pattern (values in [0,1)).
__global__ void rowstats_kernel(const float* __restrict__ md, float2* __restrict__ rs) {
    int warp = threadIdx.x >> 5, lane = threadIdx.x & 31;
    int row = blockIdx.x * 8 + warp;
    const float* p = md + (size_t)row * NN + lane;
    unsigned mu[64];
    float mn = 1e30f;
#pragma unroll
    for (int i = 0; i < 64; ++i) {
        float x = p[i * 32];
        mn = fminf(mn, x);
        mu[i] = __float_as_uint(x);
    }
#pragma unroll
    for (int off = 16; off; off >>= 1)
        mn = fminf(mn, __shfl_xor_sync(FULLMASK, mn, off));

    unsigned lo = 0u, hi = 0x3F800000u;  // bit patterns of [0,1)
    while (hi - lo > 1u) {
        unsigned mid = (lo + hi) >> 1;
        int c = 0;
#pragma unroll
        for (int i = 0; i < 64; ++i) c += (mu[i] <= mid) ? 1 : 0;
        c = __reduce_add_sync(FULLMASK, c);
        if (c >= KTH) hi = mid; else lo = mid;
    }
    if (lane == 0) rs[row] = make_float2(mn, __uint_as_float(hi));
}

// ---------------- encoder: gelu(inputs @ en_W + en_b), K=3 ----------------
__global__ void enc_kernel(const float* __restrict__ inp, const float* __restrict__ W,
                           const float* __restrict__ bvec, float* __restrict__ out) {
    int token = blockIdx.x, c = threadIdx.x;
    float x0 = inp[token * 3 + 0];
    float x1 = inp[token * 3 + 1];
    float x2 = inp[token * 3 + 2];
    float s = bvec[c];
    s = fmaf(x0, W[c], s);
    s = fmaf(x1, W[HID + c], s);
    s = fmaf(x2, W[2 * HID + c], s);
    out[(size_t)token * HID + c] = gelu_f(s);
}

// ---------------- repack head weights (H,HID,VD) -> (HID, H*VD) ----------------
__global__ void repack_kernel(const float* __restrict__ w, float* __restrict__ wc) {
    int idx = blockIdx.x * 256 + threadIdx.x;  // 16384 total
    int k = idx >> 7, c = idx & 127;
    wc[idx] = w[(c >> 4) * (HID * VD) + k * VD + (c & 15)];
}

// ---------------- 4096x128 @ 128x128 GEMM, tiled 32 rows x 64 cols ---------
// Grid (BN/32, 2), 256 threads, 48KB smem -> 4 CTAs/SM. Warp w owns rows
// w*4..w*4+3; lane owns cols {2*lane, 2*lane+1} (packed ull from smem).
// Per k: 1 LDS.64 (w pair) + 4 broadcast LDS.32 (a) + 4 packs (ALU) + 4 FMA2.
__global__ void __launch_bounds__(256) gemm3_kernel(
    const float* __restrict__ A, const float* __restrict__ W,
    const float* __restrict__ bias, const float* __restrict__ res,
    float* __restrict__ out, int act)
{
    extern __shared__ float sm[];
    float* Ws = sm;              // [128][64]
    float* As = sm + 128 * 64;   // [32][128]

    int tid = threadIdx.x, lane = tid & 31, warp = tid >> 5;
    int row0 = blockIdx.x * 32;
    int cbase = blockIdx.y * 64;

    // stage W half: 128 k-rows x 16 float4
#pragma unroll
    for (int idx = tid; idx < 128 * 16; idx += 256) {
        int k = idx >> 4, q = idx & 15;
        *(float4*)(Ws + k * 64 + q * 4) = *(const float4*)(W + (size_t)k * HID + cbase + q * 4);
    }
    // stage A tile: 32 rows x 32 float4
#pragma unroll
    for (int idx = tid; idx < 32 * 32; idx += 256) {
        int r = idx >> 5, q = idx & 31;
        *(float4*)(As + r * HID + q * 4) = *(const float4*)(A + (size_t)(row0 + r) * HID + q * 4);
    }
    __syncthreads();

    ull acc[4] = {0ull, 0ull, 0ull, 0ull};
    const ull* Wu = (const ull*)Ws;          // [k][32]
    const float* a0 = As + warp * 4 * HID;

#pragma unroll 8
    for (int k = 0; k < HID; ++k) {
        ull wp = Wu[k * 32 + lane];
        float x0 = a0[0 * HID + k];
        float x1 = a0[1 * HID + k];
        float x2 = a0[2 * HID + k];
        float x3 = a0[3 * HID + k];
        acc[0] = fma2(pack2(x0, x0), wp, acc[0]);
        acc[1] = fma2(pack2(x1, x1), wp, acc[1]);
        acc[2] = fma2(pack2(x2, x2), wp, acc[2]);
        acc[3] = fma2(pack2(x3, x3), wp, acc[3]);
    }

    float b0 = 0.f, b1 = 0.f;
    if (bias) {
        float2 bv = *(const float2*)(bias + cbase + 2 * lane);
        b0 = bv.x; b1 = bv.y;
    }
#pragma unroll
    for (int i = 0; i < 4; ++i) {
        int row = row0 + warp * 4 + i;
        float o0, o1;
        unpack2(acc[i], o0, o1);
        o0 += b0; o1 += b1;
        if (res) {
            float2 rv = *(const float2*)(res + (size_t)row * HID + cbase + 2 * lane);
            o0 += rv.x; o1 += rv.y;
        }
        if (act) { o0 = gelu_f(o0); o1 = gelu_f(o1); }
        *(float2*)(out + (size_t)row * HID + cbase + 2 * lane) = make_float2(o0, o1);
    }
}

// ---------------- fused percentile-softmax attention + gelu ----------------
// CTA: 512 threads = 16 warps x 2 rows = 32 rows, one (b,h). Full v (2048x16)
// in smem, stride 18 (conflict-free LDS.64). Lane <-> j; depth-4 prefetch
// ring on the m_dist loads covers the ~260cyc L2 latency. exp once per (i,j);
// 16 dims accumulated as 8 packed f32x2 FMAs.
template <int MASKED>
__global__ void __launch_bounds__(512, 1) attn3_kernel(
    const float* __restrict__ md, const float* __restrict__ v,
    const float* __restrict__ rvec, const float2* __restrict__ rs,
    float* __restrict__ out)
{
    extern __shared__ float vs[];   // [2048][18]
    int b = blockIdx.z, h = blockIdx.y;
    float rr = rvec[h];
    float r2 = rr * rr;
    const float L2E = 1.4426950408889634f;
    float nr2l = -r2 * L2E;

    int tid = threadIdx.x;
    int lane = tid & 31, warp = tid >> 5;
    int i0 = blockIdx.x * 32 + warp * 2;

    // stage full v_h into smem
    const float* vg = v + (size_t)b * NN * HID + h * VD;
    for (int idx = tid; idx < NN * 8; idx += 512) {
        int jj = idx >> 3, dd = (idx & 7) << 1;
        float2 val = *(const float2*)(vg + (size_t)jj * HID + dd);
        *(float2*)(vs + jj * 18 + dd) = val;
    }

    float msdl[2], s102[2], wsum[2];
    ull acc[2][8];
#pragma unroll
    for (int g = 0; g < 2; ++g) {
        float2 st = rs[b * NN + i0 + g];
        msdl[g] = (st.x * r2) * L2E;  // st.x*r2 == min_j(sd) exactly (monotone)
        s102[g] = st.y;
        wsum[g] = 0.f;
#pragma unroll
        for (int d = 0; d < 8; ++d) acc[g][d] = 0ull;
    }

    const float* mrow = md + ((size_t)b * NN + i0) * NN + lane;

    __syncthreads();

    // prime depth-4 prefetch ring
    float mr[2][4];
#pragma unroll
    for (int d = 0; d < 4; ++d) {
#pragma unroll
        for (int g = 0; g < 2; ++g) mr[g][d] = mrow[(size_t)g * NN + 32 * d];
    }

#pragma unroll 4
    for (int t = 0; t < NN / 32; ++t) {
        int slot = t & 3;
        int j = lane + 32 * t;

        const ull* vrow = (const ull*)(vs + j * 18);
        ull v0 = vrow[0], v1 = vrow[1], v2 = vrow[2], v3 = vrow[3];
        ull v4 = vrow[4], v5 = vrow[5], v6 = vrow[6], v7 = vrow[7];

        float m0 = mr[0][slot];
        float m1 = mr[1][slot];

        // prefetch step t+4 (clamped; prefetches from the last 4 steps are unused)
        int tp = t + 4; if (tp > NN / 32 - 1) tp = NN / 32 - 1;
        mr[0][slot] = mrow[0 * (size_t)NN + 32 * tp];
        mr[1][slot] = mrow[1 * (size_t)NN + 32 * tp];

        {
            float e = ex2f(fmaf(m0, nr2l, msdl[0]));
            float w = MASKED ? ((m0 <= s102[0]) ? e : 0.f) : e;
            wsum[0] += w;
            ull wp = pack2(w, w);
            acc[0][0] = fma2(wp, v0, acc[0][0]);
            acc[0][1] = fma2(wp, v1, acc[0][1]);
            acc[0][2] = fma2(wp, v2, acc[0][2]);
            acc[0][3] = fma2(wp, v3, acc[0][3]);
            acc[0][4] = fma2(wp, v4, acc[0][4]);
            acc[0][5] = fma2(wp, v5, acc[0][5]);
            acc[0][6] = fma2(wp, v6, acc[0][6]);
            acc[0][7] = fma2(wp, v7, acc[0][7]);
        }
        {
            float e = ex2f(fmaf(m1, nr2l, msdl[1]));
            float w = MASKED ? ((m1 <= s102[1]) ? e : 0.f) : e;
            wsum[1] += w;
            ull wp = pack2(w, w);
            acc[1][0] = fma2(wp, v0, acc[1][0]);
            acc[1][1] = fma2(wp, v1, acc[1][1]);
            acc[1][2] = fma2(wp, v2, acc[1][2]);
            acc[1][3] = fma2(wp, v3, acc[1][3]);
            acc[1][4] = fma2(wp, v4, acc[1][4]);
            acc[1][5] = fma2(wp, v5, acc[1][5]);
            acc[1][6] = fma2(wp, v6, acc[1][6]);
            acc[1][7] = fma2(wp, v7, acc[1][7]);
        }
    }

    // butterfly reduce across 32 lanes (j slots)
#pragma unroll
    for (int off = 16; off; off >>= 1) {
#pragma unroll
        for (int g = 0; g < 2; ++g) {
            wsum[g] += __shfl_xor_sync(FULLMASK, wsum[g], off);
#pragma unroll
            for (int d = 0; d < 8; ++d) {
                ull o = __shfl_xor_sync(FULLMASK, acc[g][d], off);
                acc[g][d] = add2(acc[g][d], o);
            }
        }
    }

    if (lane < 2) {
        int g = lane;
        float inv = 1.0f / wsum[g];
        float o[16];
#pragma unroll
        for (int d = 0; d < 8; ++d) unpack2(acc[g][d], o[2 * d], o[2 * d + 1]);
#pragma unroll
        for (int e = 0; e < 16; ++e) o[e] = gelu_f(o[e] * inv);
        float* dst = out + (size_t)(b * NN + i0 + g) * HID + h * VD;
        *(float4*)(dst + 0)  = make_float4(o[0],  o[1],  o[2],  o[3]);
        *(float4*)(dst + 4)  = make_float4(o[4],  o[5],  o[6],  o[7]);
        *(float4*)(dst + 8)  = make_float4(o[8],  o[9],  o[10], o[11]);
        *(float4*)(dst + 12) = make_float4(o[12], o[13], o[14], o[15]);
    }
}

// ---------------- final 128 -> 1 projection ----------------
__global__ void final_kernel(const float* __restrict__ t, const float* __restrict__ W,
                             const float* __restrict__ bvec, float* __restrict__ out) {
    int warp = threadIdx.x >> 5, lane = threadIdx.x & 31;
    int token = blockIdx.x * 8 + warp;
    const float* p = t + (size_t)token * HID;
    float s = 0.f;
#pragma unroll
    for (int i = 0; i < 4; ++i) s = fmaf(p[lane + 32 * i], W[lane + 32 * i], s);
#pragma unroll
    for (int off = 16; off; off >>= 1) s += __shfl_xor_sync(FULLMASK, s, off);
    if (lane == 0) out[token] = s + bvec[0];
}

// ---------------- orchestration ----------------
static float* symf(const void* sym) {
    void* p = nullptr;
    cudaGetSymbolAddress(&p, sym);
    return (float*)p;
}

extern "C" void kernel_launch(void* const* d_in, const int* in_sizes, int n_in,
                              void* d_out, int out_size) {
    const float* md      = (const float*)d_in[0];
    const float* inputs  = (const float*)d_in[1];
    const float* en_W    = (const float*)d_in[2];
    const float* en_b    = (const float*)d_in[3];
    const float* down_r  = (const float*)d_in[4];
    const float* down_w  = (const float*)d_in[5];
    const float* mlp1_W1 = (const float*)d_in[6];
    const float* mlp1_b1 = (const float*)d_in[7];
    const float* mlp1_W2 = (const float*)d_in[8];
    const float* mlp1_b2 = (const float*)d_in[9];
    const float* w1_W    = (const float*)d_in[10];
    const float* w1_b    = (const float*)d_in[11];
    const float* pa_r    = (const float*)d_in[12];
    const float* pa_w    = (const float*)d_in[13];
    const float* blk_W1  = (const float*)d_in[14];
    const float* blk_b1  = (const float*)d_in[15];
    const float* blk_W2  = (const float*)d_in[16];
    const float* blk_b2  = (const float*)d_in[17];
    const float* wi_W    = (const float*)d_in[18];
    const float* wi_b    = (const float*)d_in[19];
    const float* up_r    = (const float*)d_in[20];
    const float* up_w    = (const float*)d_in[21];
    const float* mlp2_W1 = (const float*)d_in[22];
    const float* mlp2_b1 = (const float*)d_in[23];
    const float* mlp2_W2 = (const float*)d_in[24];
    const float* mlp2_b2 = (const float*)d_in[25];
    const float* w2_W    = (const float*)d_in[26];
    const float* w2_b    = (const float*)d_in[27];
    const float* de_W1   = (const float*)d_in[28];
    const float* de_b1   = (const float*)d_in[29];
    const float* de_W2   = (const float*)d_in[30];
    const float* de_b2   = (const float*)d_in[31];
    float* outp = (float*)d_out;

    float*  en = symf(g_en);
    float*  x  = symf(g_x);
    float*  hb = symf(g_h);
    float*  tb = symf(g_t);
    float*  rb = symf(g_r);
    float*  vb = symf(g_v);
    float*  wc = symf(g_wcat);
    float2* rsp;
    { void* p = nullptr; cudaGetSymbolAddress(&p, g_rowstats); rsp = (float2*)p; }

    cudaFuncSetAttribute(gemm3_kernel, cudaFuncAttributeMaxDynamicSharedMemorySize, GEMM_SMEM);
    cudaFuncSetAttribute(attn3_kernel<0>, cudaFuncAttributeMaxDynamicSharedMemorySize, ATTN_SMEM);
    cudaFuncSetAttribute(attn3_kernel<1>, cudaFuncAttributeMaxDynamicSharedMemorySize, ATTN_SMEM);

    dim3 ggrid(BN / 32, 2);
    dim3 agrid(NN / 32, HH, BB);

    rowstats_kernel<<<BN / 8, 256>>>(md, rsp);
    enc_kernel<<<BN, HID>>>(inputs, en_W, en_b, en);

    // ---- stage 1 (input en, masked mhpa) ----
    // NOTE: w1 gemm placed BEFORE attn so ncu (-s 5 -c 1) captures attn3.
    repack_kernel<<<64, 256>>>(down_w, wc);
    gemm3_kernel<<<ggrid, 256, GEMM_SMEM>>>(en, wc, nullptr, nullptr, vb, 0);
    gemm3_kernel<<<ggrid, 256, GEMM_SMEM>>>(en, w1_W, w1_b, nullptr, rb, 0);
    attn3_kernel<1><<<agrid, 512, ATTN_SMEM>>>(md, vb, down_r, rsp, hb);
    gemm3_kernel<<<ggrid, 256, GEMM_SMEM>>>(hb, mlp1_W1, mlp1_b1, nullptr, tb, 1);
    gemm3_kernel<<<ggrid, 256, GEMM_SMEM>>>(tb, mlp1_W2, mlp1_b2, rb, x, 1);

    // ---- 4 unmasked blocks ----
    for (int i = 0; i < 4; ++i) {
        repack_kernel<<<64, 256>>>(pa_w + (size_t)i * HH * HID * VD, wc);
        gemm3_kernel<<<ggrid, 256, GEMM_SMEM>>>(x, wc, nullptr, nullptr, vb, 0);
        gemm3_kernel<<<ggrid, 256, GEMM_SMEM>>>(x, wi_W + (size_t)i * HID * HID, wi_b + (size_t)i * HID, nullptr, rb, 0);
        attn3_kernel<0><<<agrid, 512, ATTN_SMEM>>>(md, vb, pa_r + (size_t)i * HH, rsp, hb);
        gemm3_kernel<<<ggrid, 256, GEMM_SMEM>>>(hb, blk_W1 + (size_t)i * HID * HID, blk_b1 + (size_t)i * HID, nullptr, tb, 1);
        gemm3_kernel<<<ggrid, 256, GEMM_SMEM>>>(tb, blk_W2 + (size_t)i * HID * HID, blk_b2 + (size_t)i * HID, rb, x, 1);
    }

    // ---- stage 2 (masked mhpa) ----
    repack_kernel<<<64, 256>>>(up_w, wc);
    gemm3_kernel<<<ggrid, 256, GEMM_SMEM>>>(x, wc, nullptr, nullptr, vb, 0);
    gemm3_kernel<<<ggrid, 256, GEMM_SMEM>>>(x, w2_W, w2_b, nullptr, rb, 0);
    attn3_kernel<1><<<agrid, 512, ATTN_SMEM>>>(md, vb, up_r, rsp, hb);
    gemm3_kernel<<<ggrid, 256, GEMM_SMEM>>>(hb, mlp2_W1, mlp2_b1, nullptr, tb, 1);
    gemm3_kernel<<<ggrid, 256, GEMM_SMEM>>>(tb, mlp2_W2, mlp2_b2, rb, x, 1);   // x = de

    // ---- decoder ----
    gemm3_kernel<<<ggrid, 256, GEMM_SMEM>>>(x, de_W1, de_b1, nullptr, tb, 1);
    final_kernel<<<BN / 8, 256>>>(tb, de_W2, de_b2, outp);
}